// round 6
// baseline (speedup 1.0000x reference)
#include <cuda_runtime.h>
#include <cstdint>
#include <cmath>

// FIRE bias: out[1,H,S,S], H=12, S=2048, W=32.
// nd[i,j] = LR[|i-j|] * invLN[i]; bias[h] piecewise-linear in nd (<=32 ReLU knees).
// Persistent blocks: grid=444 (148 SM x occ 3); i-independent slope/intercept table
// loaded to shared ONCE per block; per-row work = 2 LDG + sLRT fill + 1 barrier.

#define SDIM 2048
#define HDIM 12
#define WDIM 32
#define NREG 33
#define GRID 444

__device__ float  g_LR[SDIM];
__device__ float  g_invLN[SDIM];
__device__ float  g_LN[SDIM];
__device__ float  g_sortedT[WDIM];
__device__ float2 g_tab[NREG * HDIM];   // {slope, intercept} (unscaled)

__global__ void fire_pre(const float* __restrict__ w1,
                         const float* __restrict__ b1,
                         const float* __restrict__ w2,
                         const float* __restrict__ b2,
                         const float* __restrict__ cp,
                         const float* __restrict__ Lm,
                         const float* __restrict__ iL) {
    __shared__ float sW1[WDIM], sB1[WDIM], sT[WDIM];
    __shared__ int   sRank[WDIM];
    const int tid = threadIdx.x;
    const float c   = *cp;
    const float thr = fabsf((*Lm) * (*iL));

    for (int d = tid; d < SDIM; d += blockDim.x) {
        g_LR[d] = logf(((float)d + 1e-6f) * c + 1.0f + 1e-6f);
        float pn = fmaxf((float)d, thr) + 1e-6f;
        float ln = logf(fabsf(c * pn) + 1.0f + 1e-6f);
        g_LN[d] = ln;
        g_invLN[d] = 1.0f / ln;
    }

    if (tid < WDIM) { sW1[tid] = w1[tid]; sB1[tid] = b1[tid]; }
    __syncthreads();
    if (tid < WDIM) {
        float w1v = sW1[tid];
        sT[tid] = (w1v != 0.0f) ? (-sB1[tid] / w1v) : 0.0f;
    }
    __syncthreads();
    if (tid < WDIM) {
        float t = sT[tid];
        int r = 0;
        for (int k = 0; k < WDIM; k++) {
            float tk = sT[k];
            if (tk < t || (tk == t && k < tid)) r++;
        }
        sRank[tid] = r;
        g_sortedT[r] = t;
    }
    __syncthreads();
    if (tid < NREG * HDIM) {
        const int r = tid / HDIM;
        const int h = tid % HDIM;
        float sl = 0.0f, ic = 0.0f;
        for (int w = 0; w < WDIM; w++) {
            const float w1v = sW1[w], b1v = sB1[w];
            bool act;
            if (w1v > 0.0f)      act = (sRank[w] < r);
            else if (w1v < 0.0f) act = (sRank[w] >= r);
            else                 act = (b1v > 0.0f);
            if (act) {
                const float w2v = w2[h * WDIM + w];
                sl += w1v * w2v;
                ic += b1v * w2v;
            }
        }
        g_tab[tid] = make_float2(sl, ic + b2[h]);
    }
#if __CUDA_ARCH__ >= 900
    cudaTriggerProgrammaticLaunchCompletion();
#endif
}

__global__ __launch_bounds__(512, 3)
void fire_main(float* __restrict__ out) {
#if __CUDA_ARCH__ >= 900
    cudaGridDependencySynchronize();
#endif
    __shared__ float2 shTab[NREG * HDIM];   // i-independent: loaded once
    __shared__ float  sLRT[2][64];          // per-row t_k*LN[i], double-buffered
    const int tid = threadIdx.x;

    for (int k = tid; k < NREG * HDIM; k += 512) shTab[k] = g_tab[k];

    int buf = 0;
    for (int i = blockIdx.x; i < SDIM; i += GRID) {
        const float invln = g_invLN[i];
        if (tid < 64) {
            const float ln = g_LN[i];
            sLRT[buf][tid] = (tid < WDIM) ? g_sortedT[tid] * ln
                                          : __int_as_float(0x7f800000);
        }
        __syncthreads();
        const float* lrt = sLRT[buf];

        const int j0 = tid * 4;
        const float lr0 = g_LR[abs(i - j0)];
        const float lr1 = g_LR[abs(i - (j0 + 1))];
        const float lr2 = g_LR[abs(i - (j0 + 2))];
        const float lr3 = g_LR[abs(i - (j0 + 3))];

        // branchless binary search: r = #{k : LR >= t_k*LN}
        int r0 = 0, r1 = 0, r2 = 0, r3 = 0;
#pragma unroll
        for (int s = 32; s >= 1; s >>= 1) {
            r0 += (lr0 >= lrt[r0 + s - 1]) ? s : 0;
            r1 += (lr1 >= lrt[r1 + s - 1]) ? s : 0;
            r2 += (lr2 >= lrt[r2 + s - 1]) ? s : 0;
            r3 += (lr3 >= lrt[r3 + s - 1]) ? s : 0;
        }

        const float nd0 = lr0 * invln;
        const float nd1 = lr1 * invln;
        const float nd2 = lr2 * invln;
        const float nd3 = lr3 * invln;

        float* op = out + (size_t)i * SDIM + j0;
        if ((r0 == r1) & (r1 == r2) & (r2 == r3)) {
            const float2* row = shTab + r0 * HDIM;
#pragma unroll
            for (int h = 0; h < HDIM; h++) {
                const float2 sb = row[h];
                float4 v = make_float4(fmaf(sb.x, nd0, sb.y), fmaf(sb.x, nd1, sb.y),
                                       fmaf(sb.x, nd2, sb.y), fmaf(sb.x, nd3, sb.y));
                __stcs(reinterpret_cast<float4*>(op + (size_t)h * SDIM * SDIM), v);
            }
        } else {
#pragma unroll
            for (int h = 0; h < HDIM; h++) {
                const float2 a = shTab[r0 * HDIM + h];
                const float2 b = shTab[r1 * HDIM + h];
                const float2 cc = shTab[r2 * HDIM + h];
                const float2 d = shTab[r3 * HDIM + h];
                float4 v = make_float4(fmaf(a.x, nd0, a.y), fmaf(b.x, nd1, b.y),
                                       fmaf(cc.x, nd2, cc.y), fmaf(d.x, nd3, d.y));
                __stcs(reinterpret_cast<float4*>(op + (size_t)h * SDIM * SDIM), v);
            }
        }
        buf ^= 1;
    }
}

extern "C" void kernel_launch(void* const* d_in, const int* in_sizes, int n_in,
                              void* d_out, int out_size) {
    // inputs: x(unused), w1[32], b1[32], w2[12*32], b2[12], c, L_multiplier, init_L
    const float* w1 = (const float*)d_in[1];
    const float* b1 = (const float*)d_in[2];
    const float* w2 = (const float*)d_in[3];
    const float* b2 = (const float*)d_in[4];
    const float* c  = (const float*)d_in[5];
    const float* Lm = (const float*)d_in[6];
    const float* iL = (const float*)d_in[7];
    (void)in_sizes; (void)n_in; (void)out_size;

    fire_pre<<<1, 512>>>(w1, b1, w2, b2, c, Lm, iL);

    cudaLaunchConfig_t cfg = {};
    cfg.gridDim  = dim3(GRID);
    cfg.blockDim = dim3(512);
    cfg.dynamicSmemBytes = 0;
    cfg.stream = 0;
    cudaLaunchAttribute attrs[1];
    attrs[0].id = cudaLaunchAttributeProgrammaticStreamSerialization;
    attrs[0].val.programmaticStreamSerializationAllowed = 1;
    cfg.attrs = attrs;
    cfg.numAttrs = 1;
    cudaLaunchKernelEx(&cfg, fire_main, (float*)d_out);
}

// round 9
// speedup vs baseline: 1.1359x; 1.1359x over previous
#include <cuda_runtime.h>
#include <cstdint>
#include <cmath>

// FIRE bias: out[1,H,S,S], H=12, S=2048, W=32.
// nd(i,j) = LR(|i-j|) * invLN(i); bias[h] piecewise-linear in nd (<=32 ReLU knees).
// LR computed inline (__logf) -> no LDG chain. Region: binary search for the first
// of a thread's 4 consecutive d's, then monotone incremental walk for the rest.
// invLN folded into the per-block slope table.

#define SDIM 2048
#define HDIM 12
#define WDIM 32
#define NREG 33

__device__ float  g_c, g_thr;
__device__ float  g_sortedT[WDIM];
__device__ float2 g_tab[NREG * HDIM];   // {slope, intercept} (unscaled)

__global__ void fire_pre(const float* __restrict__ w1,
                         const float* __restrict__ b1,
                         const float* __restrict__ w2,
                         const float* __restrict__ b2,
                         const float* __restrict__ cp,
                         const float* __restrict__ Lm,
                         const float* __restrict__ iL) {
    __shared__ float sW1[WDIM], sB1[WDIM], sT[WDIM];
    __shared__ int   sRank[WDIM];
    const int tid = threadIdx.x;
    const float c   = *cp;
    const float thr = fabsf((*Lm) * (*iL));
    if (tid == 0) { g_c = c; g_thr = thr; }

    if (tid < WDIM) { sW1[tid] = w1[tid]; sB1[tid] = b1[tid]; }
    __syncthreads();
    if (tid < WDIM) {
        float w1v = sW1[tid];
        sT[tid] = (w1v != 0.0f) ? (-sB1[tid] / w1v) : 0.0f;
    }
    __syncthreads();
    if (tid < WDIM) {
        float t = sT[tid];
        int r = 0;
        for (int k = 0; k < WDIM; k++) {
            float tk = sT[k];
            if (tk < t || (tk == t && k < tid)) r++;
        }
        sRank[tid] = r;
        g_sortedT[r] = t;
    }
    __syncthreads();
    if (tid < NREG * HDIM) {
        const int r = tid / HDIM;
        const int h = tid % HDIM;
        float sl = 0.0f, ic = 0.0f;
        for (int w = 0; w < WDIM; w++) {
            const float w1v = sW1[w], b1v = sB1[w];
            bool act;
            if (w1v > 0.0f)      act = (sRank[w] < r);
            else if (w1v < 0.0f) act = (sRank[w] >= r);
            else                 act = (b1v > 0.0f);
            if (act) {
                const float w2v = w2[h * WDIM + w];
                sl += w1v * w2v;
                ic += b1v * w2v;
            }
        }
        g_tab[tid] = make_float2(sl, ic + b2[h]);
    }
#if __CUDA_ARCH__ >= 900
    cudaTriggerProgrammaticLaunchCompletion();
#endif
}

__global__ __launch_bounds__(512, 3)
void fire_main(float* __restrict__ out) {
#if __CUDA_ARCH__ >= 900
    cudaGridDependencySynchronize();
#endif
    __shared__ float2 shTab[NREG * HDIM];   // slope pre-multiplied by invLN(i)
    __shared__ float  sLRT[64];             // t_k * LN(i), padded with +inf
    const int tid = threadIdx.x;
    const int i   = blockIdx.x;

    const float c   = g_c;
    const float thr = g_thr;
    // log-norm for this row (uniform across block; cheap MUFU math)
    const float pn    = fmaxf((float)i, thr) + 1e-6f;
    const float ln    = __logf(fabsf(c * pn) + 1.000001f);
    const float invln = __fdividef(1.0f, ln);

    for (int k = tid; k < NREG * HDIM; k += 512) {
        float2 v = g_tab[k];
        v.x *= invln;
        shTab[k] = v;
    }
    if (tid < 64)
        sLRT[tid] = (tid < WDIM) ? g_sortedT[tid] * ln : __int_as_float(0x7f800000);
    __syncthreads();

    const int j0 = tid * 4;
    const float K = fmaf(1e-6f, c, 1.000001f);   // (d+eps)*c + 1 + eps = d*c + K
    const float lr0 = __logf(fmaf((float)abs(i - j0),       c, K));
    const float lr1 = __logf(fmaf((float)abs(i - (j0 + 1)), c, K));
    const float lr2 = __logf(fmaf((float)abs(i - (j0 + 2)), c, K));
    const float lr3 = __logf(fmaf((float)abs(i - (j0 + 3)), c, K));

    // binary search for lr0's region: r = #{k : lr >= t_k*LN}
    int r0 = 0;
#pragma unroll
    for (int s = 32; s >= 1; s >>= 1)
        r0 += (lr0 >= sLRT[r0 + s - 1]) ? s : 0;
    // monotone walk for the remaining consecutive d's (expected ~0 steps)
    int r1 = r0;
    while (lr1 >= sLRT[r1]) r1++;
    while (r1 > 0 && lr1 < sLRT[r1 - 1]) r1--;
    int r2 = r1;
    while (lr2 >= sLRT[r2]) r2++;
    while (r2 > 0 && lr2 < sLRT[r2 - 1]) r2--;
    int r3 = r2;
    while (lr3 >= sLRT[r3]) r3++;
    while (r3 > 0 && lr3 < sLRT[r3 - 1]) r3--;

    float* op = out + (size_t)i * SDIM + j0;
    if ((r0 == r1) & (r1 == r2) & (r2 == r3)) {
        const float2* row = shTab + r0 * HDIM;
#pragma unroll
        for (int h = 0; h < HDIM; h++) {
            const float2 sb = row[h];
            float4 v = make_float4(fmaf(sb.x, lr0, sb.y), fmaf(sb.x, lr1, sb.y),
                                   fmaf(sb.x, lr2, sb.y), fmaf(sb.x, lr3, sb.y));
            __stcs(reinterpret_cast<float4*>(op + (size_t)h * SDIM * SDIM), v);
        }
    } else {
#pragma unroll
        for (int h = 0; h < HDIM; h++) {
            const float2 a = shTab[r0 * HDIM + h];
            const float2 b = shTab[r1 * HDIM + h];
            const float2 cc = shTab[r2 * HDIM + h];
            const float2 d = shTab[r3 * HDIM + h];
            float4 v = make_float4(fmaf(a.x, lr0, a.y), fmaf(b.x, lr1, b.y),
                                   fmaf(cc.x, lr2, cc.y), fmaf(d.x, lr3, d.y));
            __stcs(reinterpret_cast<float4*>(op + (size_t)h * SDIM * SDIM), v);
        }
    }
}

extern "C" void kernel_launch(void* const* d_in, const int* in_sizes, int n_in,
                              void* d_out, int out_size) {
    // inputs: x(unused), w1[32], b1[32], w2[12*32], b2[12], c, L_multiplier, init_L
    const float* w1 = (const float*)d_in[1];
    const float* b1 = (const float*)d_in[2];
    const float* w2 = (const float*)d_in[3];
    const float* b2 = (const float*)d_in[4];
    const float* c  = (const float*)d_in[5];
    const float* Lm = (const float*)d_in[6];
    const float* iL = (const float*)d_in[7];
    (void)in_sizes; (void)n_in; (void)out_size;

    fire_pre<<<1, 512>>>(w1, b1, w2, b2, c, Lm, iL);

    cudaLaunchConfig_t cfg = {};
    cfg.gridDim  = dim3(SDIM);
    cfg.blockDim = dim3(512);
    cfg.dynamicSmemBytes = 0;
    cfg.stream = 0;
    cudaLaunchAttribute attrs[1];
    attrs[0].id = cudaLaunchAttributeProgrammaticStreamSerialization;
    attrs[0].val.programmaticStreamSerializationAllowed = 1;
    cfg.attrs = attrs;
    cfg.numAttrs = 1;
    cudaLaunchKernelEx(&cfg, fire_main, (float*)d_out);
}